// round 16
// baseline (speedup 1.0000x reference)
#include <cuda_runtime.h>
#include <cuda_fp16.h>
#include <cstdint>

// Problem constants
#define BB   2
#define QQ   2048
#define KK   2048
#define EMB  2048
#define HH   32
#define DD   64
#define ROWS (BB * QQ)          // 4096

#define LOG2E 1.4426950408889634f

// ---------------- scratch (device globals; no allocation allowed) ----------
__device__ __half g_xq [ROWS * EMB];
__device__ __half g_xkv[ROWS * EMB];
__device__ __half g_bh [BB * QQ * KK];   // bias * log2e, fp16
__device__ __half g_qs [ROWS * EMB];
__device__ __half g_ks [ROWS * EMB];
__device__ __half g_vs [ROWS * EMB];
__device__ __half g_cs [ROWS * EMB];

__device__ __half g_wqt[EMB * EMB];
__device__ __half g_wkt[EMB * EMB];
__device__ __half g_wvt[EMB * EMB];
__device__ __half g_wot[EMB * EMB];

// ---------------- helpers ---------------------------------------------------
__device__ __forceinline__ uint32_t smem_u32(const void* p) {
    uint32_t a;
    asm("{ .reg .u64 t; cvta.to.shared.u64 t, %1; cvt.u32.u64 %0, t; }"
        : "=r"(a) : "l"(p));
    return a;
}
__device__ __forceinline__ float ex2f(float x) {
    float y; asm("ex2.approx.f32 %0, %1;" : "=f"(y) : "f"(x)); return y;
}

#define CP_ASYNC16(dst, src) \
    asm volatile("cp.async.cg.shared.global [%0], [%1], 16;" :: "r"(dst), "l"(src))
#define CP_COMMIT() asm volatile("cp.async.commit_group;" ::: "memory")
#define CP_WAIT(n)  asm volatile("cp.async.wait_group %0;" :: "n"(n) : "memory")

__device__ __forceinline__ void ldsm_x4(uint32_t* d, uint32_t addr) {
    asm volatile("ldmatrix.sync.aligned.m8n8.x4.shared.b16 {%0,%1,%2,%3}, [%4];"
                 : "=r"(d[0]), "=r"(d[1]), "=r"(d[2]), "=r"(d[3]) : "r"(addr));
}
__device__ __forceinline__ void ldsm_x4_t(uint32_t* d, uint32_t addr) {
    asm volatile("ldmatrix.sync.aligned.m8n8.x4.trans.shared.b16 {%0,%1,%2,%3}, [%4];"
                 : "=r"(d[0]), "=r"(d[1]), "=r"(d[2]), "=r"(d[3]) : "r"(addr));
}
__device__ __forceinline__ void mma16816(float* d, const uint32_t* a, const uint32_t* b) {
    asm volatile(
        "mma.sync.aligned.m16n8k16.row.col.f32.f16.f16.f32 "
        "{%0,%1,%2,%3}, {%4,%5,%6,%7}, {%8,%9}, {%0,%1,%2,%3};"
        : "+f"(d[0]), "+f"(d[1]), "+f"(d[2]), "+f"(d[3])
        : "r"(a[0]), "r"(a[1]), "r"(a[2]), "r"(a[3]), "r"(b[0]), "r"(b[1]));
}

__device__ __forceinline__ uint32_t pack2h(float a, float b) {
    __half2 h = __floats2half2_rn(a, b);
    return *(uint32_t*)&h;
}

// ============================================================================
// Elementwise fp32 -> fp16 convert, 16 elems/thread (MLP=4);
// blockIdx.y selects tensor (xq, xkv, bias*log2e)
// ============================================================================
__global__ __launch_bounds__(256)
void conv_all_kernel(const float* __restrict__ x0, __half* __restrict__ y0,
                     const float* __restrict__ x1, __half* __restrict__ y1,
                     const float* __restrict__ x2, __half* __restrict__ y2)
{
    const float* x = (blockIdx.y == 0) ? x0 : (blockIdx.y == 1) ? x1 : x2;
    __half* y = (blockIdx.y == 0) ? y0 : (blockIdx.y == 1) ? y1 : y2;
    const float sc = (blockIdx.y == 2) ? LOG2E : 1.0f;
    const size_t base = (size_t)blockIdx.x * 4096 + threadIdx.x * 4;

    float4 v[4];
#pragma unroll
    for (int j = 0; j < 4; j++)
        v[j] = *(const float4*)(x + base + j * 1024);
#pragma unroll
    for (int j = 0; j < 4; j++) {
        __half2* p = (__half2*)(y + base + j * 1024);
        p[0] = __floats2half2_rn(v[j].x * sc, v[j].y * sc);
        p[1] = __floats2half2_rn(v[j].z * sc, v[j].w * sc);
    }
}

// ============================================================================
// Weight transpose to single fp16, blockIdx.z selects weight
// ============================================================================
__global__ __launch_bounds__(256)
void wconv_all_kernel(const float* __restrict__ w0, __half* __restrict__ t0,
                      const float* __restrict__ w1, __half* __restrict__ t1,
                      const float* __restrict__ w2, __half* __restrict__ t2,
                      const float* __restrict__ w3, __half* __restrict__ t3)
{
    const float* w = (blockIdx.z == 0) ? w0 : (blockIdx.z == 1) ? w1
                    : (blockIdx.z == 2) ? w2 : w3;
    __half* th = (blockIdx.z == 0) ? t0 : (blockIdx.z == 1) ? t1
                : (blockIdx.z == 2) ? t2 : t3;
    __shared__ float tile[32][33];
    const int bx = blockIdx.x * 32;
    const int by = blockIdx.y * 32;
    const int tx = threadIdx.x % 32;
    const int ty = threadIdx.x / 32;
#pragma unroll
    for (int j = 0; j < 32; j += 8)
        tile[ty + j][tx] = w[(size_t)(by + ty + j) * 2048 + bx + tx];
    __syncthreads();
#pragma unroll
    for (int j = 0; j < 32; j += 8)
        th[(size_t)(bx + ty + j) * 2048 + by + tx] = __float2half(tile[tx][ty + j]);
}

// ============================================================================
// fp16 GEMM body: C = alpha * A*B^T.  128x128 tile, 8 warps, K-chunk 64,
// 3-STAGE ring (one extra iter of load slack), one sync per iter, x4 ldmatrix.
// ============================================================================
#define TS      144
#define TILE_B  (128 * TS)           // 18432 per tile
#define GNST    3
#define GEMM_SMEM (GNST * 2 * TILE_B)   // 110592

__device__ __forceinline__
void gemm_body(const __half* __restrict__ A, const __half* __restrict__ B,
               float* __restrict__ Cf, __half* __restrict__ Ch, float alpha,
               char* smg, int bx, int by)
{
    const uint32_t smb = smem_u32(smg);
    const int tid  = threadIdx.x;
    const int wid  = tid / 32;
    const int lane = tid % 32;
    const int block_row = by * 128;
    const int block_col = bx * 128;

    const int wm = (wid & 1) * 64;
    const int wn = (wid >> 1) * 32;

    const uint32_t a_lm  = (wm + (lane & 15)) * TS + (lane >> 4) * 16;
    const uint32_t b_lm4 = (wn + (lane & 7)) * TS + ((lane >> 3) & 1) * 16
                         + (lane >> 4) * (8 * TS);

    float acc[4][4][4];
#pragma unroll
    for (int i = 0; i < 4; i++)
#pragma unroll
        for (int j = 0; j < 4; j++)
#pragma unroll
            for (int r = 0; r < 4; r++) acc[i][j][r] = 0.f;

#define G_LOAD(kk, bufi) do {                                                  \
    const uint32_t bb_ = smb + (bufi) * (2 * TILE_B);                          \
    _Pragma("unroll")                                                          \
    for (int j_ = 0; j_ < 4; j_++) {                                           \
        const int idx_ = tid + 256 * j_;                                       \
        const int r_ = idx_ >> 3;                                              \
        const int c_ = idx_ & 7;                                               \
        CP_ASYNC16(bb_ + r_ * TS + c_ * 16,                                    \
                   A + (size_t)(block_row + r_) * 2048 + (kk) + c_ * 8);       \
        CP_ASYNC16(bb_ + TILE_B + r_ * TS + c_ * 16,                           \
                   B + (size_t)(block_col + r_) * 2048 + (kk) + c_ * 8);       \
    }                                                                          \
} while (0)

    G_LOAD(0, 0);
    CP_COMMIT();
    G_LOAD(64, 1);
    CP_COMMIT();

    for (int i = 0; i < 32; i++) {
        if (i < 31) { CP_WAIT(1); } else { CP_WAIT(0); }
        __syncthreads();                 // orders readers of buf (i+2)%3 too
        if (i + 2 < 32) {
            G_LOAD((i + 2) * 64, (i + 2) % GNST);
            CP_COMMIT();
        }
        const uint32_t base = smb + (i % GNST) * (2 * TILE_B);
#pragma unroll
        for (int ks = 0; ks < 4; ks++) {
            uint32_t afrag[4][4];
#pragma unroll
            for (int mt = 0; mt < 4; mt++)
                ldsm_x4(afrag[mt], base + a_lm + mt * (16 * TS) + ks * 32);
#pragma unroll
            for (int nt2 = 0; nt2 < 2; nt2++) {
                uint32_t bfr[4];
                ldsm_x4(bfr, base + TILE_B + b_lm4 + nt2 * (16 * TS) + ks * 32);
#pragma unroll
                for (int mt = 0; mt < 4; mt++) {
                    mma16816(acc[mt][2 * nt2],     afrag[mt], bfr);
                    mma16816(acc[mt][2 * nt2 + 1], afrag[mt], bfr + 2);
                }
            }
        }
    }

#pragma unroll
    for (int mt = 0; mt < 4; mt++) {
        const int row = block_row + wm + mt * 16 + lane / 4;
#pragma unroll
        for (int nt = 0; nt < 4; nt++) {
            const int col = block_col + wn + nt * 8 + (lane % 4) * 2;
            float v0 = alpha * acc[mt][nt][0];
            float v1 = alpha * acc[mt][nt][1];
            float v2 = alpha * acc[mt][nt][2];
            float v3 = alpha * acc[mt][nt][3];
            if (Cf) {
                *(float2*)(Cf + (size_t)row * 2048 + col)       = make_float2(v0, v1);
                *(float2*)(Cf + (size_t)(row + 8) * 2048 + col) = make_float2(v2, v3);
            } else {
                *(uint32_t*)(Ch + (size_t)row * 2048 + col)       = pack2h(v0, v1);
                *(uint32_t*)(Ch + (size_t)(row + 8) * 2048 + col) = pack2h(v2, v3);
            }
        }
    }
}

__global__ __launch_bounds__(256, 2)
void gemm_qkv_kernel(const __half* __restrict__ xq, const __half* __restrict__ xkv,
                     const __half* __restrict__ wqt, const __half* __restrict__ wkt,
                     const __half* __restrict__ wvt,
                     __half* __restrict__ qs, __half* __restrict__ ks,
                     __half* __restrict__ vs)
{
    extern __shared__ __align__(16) char smg[];
    const int z = blockIdx.z;
    const __half* A = (z == 0) ? xq : xkv;
    const __half* B = (z == 0) ? wqt : (z == 1) ? wkt : wvt;
    __half* C = (z == 0) ? qs : (z == 1) ? ks : vs;
    const float alpha = (z == 0) ? 0.125f * LOG2E : 1.0f;
    gemm_body(A, B, nullptr, C, alpha, smg, blockIdx.x, blockIdx.y);
}

__global__ __launch_bounds__(256, 2)
void gemm_out_kernel(const __half* __restrict__ cs, const __half* __restrict__ wot,
                     float* __restrict__ out)
{
    extern __shared__ __align__(16) char smg[];
    gemm_body(cs, wot, out, nullptr, 1.0f, smg, blockIdx.x, blockIdx.y);
}

// ============================================================================
// Flash attention (fp16, exp2 domain): unchanged from R15.
// ============================================================================
#define KVS 144
#define KVT (64 * KVS)
#define ATT_SMEM (3 * 2 * KVT)       // 55296

__global__ __launch_bounds__(256, 2)
void attn_mma(const __half* __restrict__ q,
              const __half* __restrict__ k,
              const __half* __restrict__ v,
              const __half* __restrict__ bias,
              __half* __restrict__ cs)
{
    extern __shared__ __align__(16) char sm[];
    const uint32_t smb = smem_u32(sm);

    const int tid  = threadIdx.x;
    const int wid  = tid / 32;
    const int lane = tid % 32;
    const int qt = blockIdx.x;
    const int h  = blockIdx.y;
    const int b  = blockIdx.z;
    const int g  = lane >> 2;
    const int t  = lane & 3;

    const int qrow  = qt * 128 + wid * 16 + g;
    const size_t arow = (size_t)(b * 2048 + qrow);
    const int dbase = h * 64;

    uint32_t qf[4][4];
    {
        const __half* q0 = q + arow * 2048 + dbase;
#pragma unroll
        for (int kk = 0; kk < 4; kk++) {
            qf[kk][0] = *(const uint32_t*)(q0 + kk * 16 + 2 * t);
            qf[kk][1] = *(const uint32_t*)(q0 + (size_t)8 * 2048 + kk * 16 + 2 * t);
            qf[kk][2] = *(const uint32_t*)(q0 + kk * 16 + 8 + 2 * t);
            qf[kk][3] = *(const uint32_t*)(q0 + (size_t)8 * 2048 + kk * 16 + 8 + 2 * t);
        }
    }

    float ctx[8][4];
#pragma unroll
    for (int nt = 0; nt < 8; nt++)
#pragma unroll
        for (int r = 0; r < 4; r++) ctx[nt][r] = 0.f;
    float m0 = -1e30f, m1 = -1e30f;
    float l0 = 0.f, l1 = 0.f;

    const int lr  = tid >> 3;
    const int lgr = tid & 7;
#define LOAD_CHUNK(kc, bufi) do {                                              \
    const uint32_t base_ = smb + (bufi) * (2 * KVT);                           \
    _Pragma("unroll")                                                          \
    for (int i_ = 0; i_ < 4; i_++) {                                           \
        const __half* s_ = (i_ < 2) ? k : v;                                   \
        const int r_ = lr + 32 * (i_ & 1);                                     \
        const int mat_ = i_ >> 1;                                              \
        const __half* src_ = s_ +                                              \
            (size_t)(b * 2048 + (kc) + r_) * 2048 + dbase + lgr * 8;           \
        CP_ASYNC16(base_ + mat_ * KVT + r_ * KVS + lgr * 16, src_);            \
    }                                                                          \
} while (0)

    LOAD_CHUNK(0, 0);
    CP_COMMIT();
    LOAD_CHUNK(64, 1);
    CP_COMMIT();

    const __half* bias_b  = bias + (size_t)b * 2048 * 2048
                          + (size_t)(qt * 128 + wid * 16 + g) * 2048;
    const __half* bias_b8 = bias_b + (size_t)8 * 2048;

    __half2 pb[8], pb8[8];
#pragma unroll
    for (int nt = 0; nt < 8; nt++) {
        pb[nt]  = *(const __half2*)(bias_b  + nt * 8 + 2 * t);
        pb8[nt] = *(const __half2*)(bias_b8 + nt * 8 + 2 * t);
    }

    const uint32_t kaddr4 = (lane & 7) * KVS + ((lane >> 3) & 1) * 16
                          + (lane >> 4) * (8 * KVS);
    const uint32_t vaddr4 = (lane & 15) * KVS + (lane >> 4) * 16;

    for (int c = 0; c < 32; c++) {
        if (c < 31) { CP_WAIT(1); } else { CP_WAIT(0); }
        __syncthreads();
        if (c + 2 < 32) {
            LOAD_CHUNK((c + 2) * 64, (c + 2) % 3);
            CP_COMMIT();
        }

        const uint32_t k_s = smb + (c % 3) * (2 * KVT);
        const uint32_t v_s = k_s + KVT;

        float s[8][4];
#pragma unroll
        for (int nt = 0; nt < 8; nt++) {
            s[nt][0] = __low2float(pb[nt]);
            s[nt][1] = __high2float(pb[nt]);
            s[nt][2] = __low2float(pb8[nt]);
            s[nt][3] = __high2float(pb8[nt]);
        }
        if (c + 1 < 32) {
            const __half* nb  = bias_b  + (c + 1) * 64;
            const __half* nb8 = bias_b8 + (c + 1) * 64;
#pragma unroll
            for (int nt = 0; nt < 8; nt++) {
                pb[nt]  = *(const __half2*)(nb  + nt * 8 + 2 * t);
                pb8[nt] = *(const __half2*)(nb8 + nt * 8 + 2 * t);
            }
        }

#pragma unroll
        for (int kk = 0; kk < 4; kk++) {
#pragma unroll
            for (int nt2 = 0; nt2 < 4; nt2++) {
                uint32_t bfr[4];
                ldsm_x4(bfr, k_s + nt2 * (16 * KVS) + kaddr4 + kk * 32);
                mma16816(s[2 * nt2],     qf[kk], bfr);
                mma16816(s[2 * nt2 + 1], qf[kk], bfr + 2);
            }
        }

        float mx0 = -1e30f, mx1 = -1e30f;
#pragma unroll
        for (int nt = 0; nt < 8; nt++) {
            mx0 = fmaxf(mx0, fmaxf(s[nt][0], s[nt][1]));
            mx1 = fmaxf(mx1, fmaxf(s[nt][2], s[nt][3]));
        }
        mx0 = fmaxf(mx0, __shfl_xor_sync(0xffffffffu, mx0, 1));
        mx0 = fmaxf(mx0, __shfl_xor_sync(0xffffffffu, mx0, 2));
        mx1 = fmaxf(mx1, __shfl_xor_sync(0xffffffffu, mx1, 1));
        mx1 = fmaxf(mx1, __shfl_xor_sync(0xffffffffu, mx1, 2));
        const float mn0 = fmaxf(m0, mx0);
        const float mn1 = fmaxf(m1, mx1);
        const float sc0 = ex2f(m0 - mn0);
        const float sc1 = ex2f(m1 - mn1);
        m0 = mn0; m1 = mn1;

        uint32_t p01[8], p23[8];
        float rs0 = 0.f, rs1 = 0.f;
#pragma unroll
        for (int nt = 0; nt < 8; nt++) {
            float e0 = ex2f(s[nt][0] - mn0);
            float e1 = ex2f(s[nt][1] - mn0);
            float e2 = ex2f(s[nt][2] - mn1);
            float e3 = ex2f(s[nt][3] - mn1);
            __half2 h01 = __floats2half2_rn(e0, e1);
            __half2 h23 = __floats2half2_rn(e2, e3);
            p01[nt] = *(uint32_t*)&h01;
            p23[nt] = *(uint32_t*)&h23;
            rs0 += __low2float(h01) + __high2float(h01);
            rs1 += __low2float(h23) + __high2float(h23);
        }
        l0 = l0 * sc0 + rs0;
        l1 = l1 * sc1 + rs1;

#pragma unroll
        for (int nt = 0; nt < 8; nt++) {
            ctx[nt][0] *= sc0; ctx[nt][1] *= sc0;
            ctx[nt][2] *= sc1; ctx[nt][3] *= sc1;
        }

#pragma unroll
        for (int j = 0; j < 4; j++) {
            const uint32_t pa[4] = {p01[2 * j], p23[2 * j], p01[2 * j + 1], p23[2 * j + 1]};
#pragma unroll
            for (int nt2 = 0; nt2 < 4; nt2++) {
                uint32_t bvr[4];
                ldsm_x4_t(bvr, v_s + j * (16 * KVS) + vaddr4 + nt2 * 32);
                mma16816(ctx[2 * nt2],     pa, bvr);
                mma16816(ctx[2 * nt2 + 1], pa, bvr + 2);
            }
        }
    }

    l0 += __shfl_xor_sync(0xffffffffu, l0, 1);
    l0 += __shfl_xor_sync(0xffffffffu, l0, 2);
    l1 += __shfl_xor_sync(0xffffffffu, l1, 1);
    l1 += __shfl_xor_sync(0xffffffffu, l1, 2);

    const float inv0 = 1.f / l0;
    const float inv1 = 1.f / l1;
#pragma unroll
    for (int nt = 0; nt < 8; nt++) {
        const int col = dbase + nt * 8 + 2 * t;
        *(uint32_t*)(cs + arow * 2048 + col) =
            pack2h(ctx[nt][0] * inv0, ctx[nt][1] * inv0);
        *(uint32_t*)(cs + (arow + 8) * 2048 + col) =
            pack2h(ctx[nt][2] * inv1, ctx[nt][3] * inv1);
    }
}

// ============================================================================
// Launch
// ============================================================================
extern "C" void kernel_launch(void* const* d_in, const int* in_sizes, int n_in,
                              void* d_out, int out_size)
{
    const float* inputs_q  = (const float*)d_in[0];
    const float* inputs_kv = (const float*)d_in[1];
    const float* bias      = (const float*)d_in[2];
    const float* wq        = (const float*)d_in[3];
    const float* wk        = (const float*)d_in[4];
    const float* wv        = (const float*)d_in[5];
    const float* wo        = (const float*)d_in[6];
    float* out = (float*)d_out;

    __half *xq, *xkv, *bh, *qs, *ks, *vs, *cs;
    __half *wqt, *wkt, *wvt, *wot;
    cudaGetSymbolAddress((void**)&xq,  g_xq);
    cudaGetSymbolAddress((void**)&xkv, g_xkv);
    cudaGetSymbolAddress((void**)&bh,  g_bh);
    cudaGetSymbolAddress((void**)&qs,  g_qs);
    cudaGetSymbolAddress((void**)&ks,  g_ks);
    cudaGetSymbolAddress((void**)&vs,  g_vs);
    cudaGetSymbolAddress((void**)&cs,  g_cs);
    cudaGetSymbolAddress((void**)&wqt, g_wqt);
    cudaGetSymbolAddress((void**)&wkt, g_wkt);
    cudaGetSymbolAddress((void**)&wvt, g_wvt);
    cudaGetSymbolAddress((void**)&wot, g_wot);

    static bool attr_done = false;
    if (!attr_done) {
        cudaFuncSetAttribute(attn_mma, cudaFuncAttributeMaxDynamicSharedMemorySize,
                             ATT_SMEM);
        cudaFuncSetAttribute(gemm_qkv_kernel, cudaFuncAttributeMaxDynamicSharedMemorySize,
                             GEMM_SMEM);
        cudaFuncSetAttribute(gemm_out_kernel, cudaFuncAttributeMaxDynamicSharedMemorySize,
                             GEMM_SMEM);
        attr_done = true;
    }

    const int n_act = ROWS * EMB;                     // 8388608
    const dim3 ggrid(EMB / 128, ROWS / 128);          // (16, 32)
    const dim3 gqkv(EMB / 128, ROWS / 128, 3);

    // Prep: 2 launches (conv 16 elems/thread; bias scaled by log2e)
    conv_all_kernel<<<dim3(n_act / 4096, 3), 256>>>(inputs_q, xq, inputs_kv, xkv,
                                                    bias, bh);
    wconv_all_kernel<<<dim3(64, 64, 4), 256>>>(wq, wqt, wk, wkt, wv, wvt, wo, wot);

    // Fused Q/K/V projections (3-stage ring)
    gemm_qkv_kernel<<<gqkv, 256, GEMM_SMEM>>>(xq, xkv, wqt, wkt, wvt, qs, ks, vs);

    // Flash attention (exp2 domain) -> single fp16 ctx
    attn_mma<<<dim3(16, 32, 2), 256, ATT_SMEM>>>(qs, ks, vs, bh, cs);

    // Output projection (3-stage ring) -> f32 out
    gemm_out_kernel<<<ggrid, 256, GEMM_SMEM>>>(cs, wot, out);
}